// round 15
// baseline (speedup 1.0000x reference)
#include <cuda_runtime.h>
#include <cuda_fp16.h>
#include <cstdint>

// Problem constants
#define B_SZ 4
#define N_SEQ 2048
#define D_MODEL 1024
#define N_HEADS 16
#define HEAD_DIM 64
#define BH (B_SZ * N_HEADS)          // 64
#define TOKENS (B_SZ * N_SEQ)        // 8192
#define QKV_COLS (3 * D_MODEL)       // 3072

// ---------------------------------------------------------------------------
// Scratch (module-static device memory; no runtime allocation)
// ---------------------------------------------------------------------------
#define QKV_ELEMS ((size_t)BH * N_SEQ * HEAD_DIM)   // 8388608
__device__ __half g_x_f[(size_t)TOKENS * D_MODEL];
__device__ __half g_wqkv_f[(size_t)QKV_COLS * D_MODEL];   // [n][k]
__device__ __half g_wout_f[(size_t)D_MODEL * D_MODEL];    // [n][k]
__device__ __half g_q_f[QKV_ELEMS];   // [bh][n][dh], pre-scaled by 0.125*log2(e)
__device__ __half g_k_f[QKV_ELEMS];   // [bh][n][dh]
__device__ __half g_vt_f[QKV_ELEMS];  // [bh][dh][n]  (transposed)
__device__ __half g_att_f[(size_t)TOKENS * D_MODEL];  // [token][h*64+dh]

// ---------------------------------------------------------------------------
// Helpers
// ---------------------------------------------------------------------------
__device__ __forceinline__ uint32_t smem_u32(const void* p) {
    uint32_t a;
    asm("{ .reg .u64 t; cvta.to.shared.u64 t, %1; cvt.u32.u64 %0, t; }"
        : "=r"(a) : "l"(p));
    return a;
}

__device__ __forceinline__ uint32_t pack_h2(float x, float y) {
    __half2 h = __floats2half2_rn(x, y);
    return *(uint32_t*)&h;
}

__device__ __forceinline__ float fexp2(float x) {
    float y;
    asm("ex2.approx.f32 %0, %1;" : "=f"(y) : "f"(x));
    return y;
}

__device__ __forceinline__ uint32_t h2exp2(uint32_t x) {
    uint32_t y;
    asm("ex2.approx.f16x2 %0, %1;" : "=r"(y) : "r"(x));
    return y;
}

#define ONES_H2 0x3C003C00u   // half2(1.0, 1.0)

#define LDSM_X4(r0, r1, r2, r3, addr) \
    asm volatile("ldmatrix.sync.aligned.m8n8.x4.shared.b16 {%0,%1,%2,%3}, [%4];" \
                 : "=r"(r0), "=r"(r1), "=r"(r2), "=r"(r3) : "r"(addr))

#define MMA_F16(c, a, b0, b1) \
    asm volatile("mma.sync.aligned.m16n8k16.row.col.f32.f16.f16.f32 " \
                 "{%0,%1,%2,%3}, {%4,%5,%6,%7}, {%8,%9}, {%0,%1,%2,%3};" \
                 : "+f"((c)[0]), "+f"((c)[1]), "+f"((c)[2]), "+f"((c)[3]) \
                 : "r"((a)[0]), "r"((a)[1]), "r"((a)[2]), "r"((a)[3]), \
                   "r"(b0), "r"(b1))

#define CP16(saddr, gptr) \
    asm volatile("cp.async.cg.shared.global [%0], [%1], 16;" \
                 :: "r"(saddr), "l"(gptr) : "memory")
#define CP_COMMIT() asm volatile("cp.async.commit_group;" ::: "memory")
#define CP_WAIT(n)  asm volatile("cp.async.wait_group %0;" :: "n"(n) : "memory")

// Q pre-scale: (1/sqrt(64)) * log2(e), so softmax runs in base-2 domain.
#define Q_SCALE 0.1803368801111244f

// ---------------------------------------------------------------------------
// Conversion kernels (fp32 -> fp16)
// ---------------------------------------------------------------------------
__global__ void conv_x_kernel(const float* __restrict__ x, __half* __restrict__ o, int n4)
{
    int idx = blockIdx.x * 256 + threadIdx.x;
    if (idx >= n4) return;
    float4 v = ((const float4*)x)[idx];
    ((uint2*)o)[idx] = make_uint2(pack_h2(v.x, v.y), pack_h2(v.z, v.w));
}

// Both weight transposes in one launch. blockIdx.x < 96 -> W_qkv, else W_out.
__global__ void conv_wt_kernel(const float* __restrict__ Wq, __half* __restrict__ oq,
                               const float* __restrict__ Wo, __half* __restrict__ oo)
{
    __shared__ float t[32][33];
    const int tx = threadIdx.x, ty = threadIdx.y;  // block (32,8)
    const float* W;
    __half* o;
    int N, n0;
    if (blockIdx.x < QKV_COLS / 32) {
        W = Wq; o = oq; N = QKV_COLS; n0 = blockIdx.x * 32;
    } else {
        W = Wo; o = oo; N = D_MODEL; n0 = (blockIdx.x - QKV_COLS / 32) * 32;
    }
    const int K = D_MODEL;
    const int k0 = blockIdx.y * 32;
#pragma unroll
    for (int s = 0; s < 4; s++)
        t[ty + 8 * s][tx] = W[(size_t)(k0 + ty + 8 * s) * N + n0 + tx];
    __syncthreads();
#pragma unroll
    for (int s = 0; s < 4; s++) {
        const int nn = ty + 8 * s, kk = tx;
        o[(size_t)(n0 + nn) * K + k0 + kk] = __float2half_rn(t[kk][nn]);
    }
}

// ---------------------------------------------------------------------------
// Warp-MMA fp16 GEMM, BK=64, 3-stage cp.async ring.
// Inner loop restructured: ALL fragments for a k16-step are loaded before any
// MMA of that step (explicit latency hiding; ptxas can't hoist at 126 regs).
// ---------------------------------------------------------------------------
#define SSTRIDE 72
#define G_ARR_B (128 * SSTRIDE * 2)          // 18432 bytes per array (128x64 fp16)
#define G_STAGE_B (2 * G_ARR_B)              // 36864 per stage (A|B)
#define G_SMEM_B (3 * G_STAGE_B)             // 110592

__global__ void __launch_bounds__(256, 2)
mma_gemm_kernel(const __half* __restrict__ A_g, const __half* __restrict__ B_g,
                const float* __restrict__ bias, float* __restrict__ C,
                int M, int N, int K, int mode)
{
    extern __shared__ __align__(16) char dsm[];
    const uint32_t sb0 = smem_u32(dsm);

    const int tid  = threadIdx.x;
    const int wid  = tid >> 5;
    const int lane = tid & 31;
    const int wr   = wid >> 1;
    const int wc   = wid & 1;

    const int row0 = blockIdx.y * 128;
    const int col0 = blockIdx.x * 128;

    float acc[2][8][4];
#pragma unroll
    for (int i = 0; i < 2; i++)
#pragma unroll
        for (int j = 0; j < 8; j++)
#pragma unroll
            for (int c = 0; c < 4; c++) acc[i][j][c] = 0.f;

    const uint32_t a_row = lane & 15;
    const uint32_t a_kof = (lane >> 4) << 3;
    const uint32_t b_nof = ((lane >> 4) << 3) + (lane & 7);
    const uint32_t b_kof = ((lane >> 3) & 1) << 3;

    uint32_t lso[4];
    const __half* ap[4];
    const __half* bp[4];
#pragma unroll
    for (int i = 0; i < 4; i++) {
        int f = i * 256 + tid;
        int r = f >> 3;
        int c = (f & 7) << 3;
        lso[i] = ((uint32_t)r * SSTRIDE + c) * 2;
        ap[i] = A_g + (size_t)(row0 + r) * K + c;
        bp[i] = B_g + (size_t)(col0 + r) * K + c;
    }

#define G_ISSUE(stage, k0_)                                                     \
    do {                                                                        \
        uint32_t sb = sb0 + (stage) * G_STAGE_B;                                \
        _Pragma("unroll")                                                       \
        for (int i = 0; i < 4; i++) {                                           \
            CP16(sb + lso[i],           ap[i] + (k0_));                         \
            CP16(sb + G_ARR_B + lso[i], bp[i] + (k0_));                         \
        }                                                                       \
        CP_COMMIT();                                                            \
    } while (0)

    const int niter = K / 64;
    G_ISSUE(0, 0);
    G_ISSUE(1, 64);

    for (int it = 0; it < niter; it++) {
        if (it + 1 < niter) { CP_WAIT(1); } else { CP_WAIT(0); }
        __syncthreads();
        if (it + 2 < niter) G_ISSUE((it + 2) % 3, (it + 2) * 64);

        const uint32_t sb  = sb0 + (it % 3) * G_STAGE_B;
        const uint32_t a_b = sb;
        const uint32_t b_b = sb + G_ARR_B;

#pragma unroll
        for (int ks = 0; ks < 4; ks++) {
            const uint32_t kk = ks * 16;
            // ---- load ALL fragments for this k-step first
            uint32_t ar[2][4], br[4][4];
#pragma unroll
            for (int i = 0; i < 2; i++) {
                uint32_t eoff = ((wr * 32 + i * 16 + a_row) * SSTRIDE + kk + a_kof) * 2;
                LDSM_X4(ar[i][0], ar[i][1], ar[i][2], ar[i][3], a_b + eoff);
            }
#pragma unroll
            for (int jp = 0; jp < 4; jp++) {
                uint32_t eoff = ((wc * 64 + jp * 16 + b_nof) * SSTRIDE + kk + b_kof) * 2;
                LDSM_X4(br[jp][0], br[jp][1], br[jp][2], br[jp][3], b_b + eoff);
            }
            // ---- then 32 back-to-back MMAs
#pragma unroll
            for (int jp = 0; jp < 4; jp++)
#pragma unroll
                for (int i = 0; i < 2; i++) {
                    MMA_F16(acc[i][2 * jp + 0], ar[i], br[jp][0], br[jp][1]);
                    MMA_F16(acc[i][2 * jp + 1], ar[i], br[jp][2], br[jp][3]);
                }
        }
    }
#undef G_ISSUE

    const int mbase = row0 + wr * 32 + (lane >> 2);
    const int nbase = col0 + wc * 64 + ((lane & 3) << 1);

    if (mode == 0) {
#pragma unroll
        for (int i = 0; i < 2; i++) {
#pragma unroll
            for (int rr = 0; rr < 2; rr++) {
                const int m  = mbase + i * 16 + rr * 8;
                const int bb = m >> 11;
                const int nn = m & 2047;
#pragma unroll
                for (int j = 0; j < 8; j++) {
                    const int jg0 = nbase + j * 8;
                    const int sel = jg0 >> 10;
                    const int hh  = (jg0 >> 6) & 15;
                    const int dh  = jg0 & 63;
                    const int bhd = bb * N_HEADS + hh;
                    float v0 = acc[i][j][rr * 2 + 0] + bias[jg0];
                    float v1 = acc[i][j][rr * 2 + 1] + bias[jg0 + 1];
                    if (sel == 0) { v0 *= Q_SCALE; v1 *= Q_SCALE; }
                    if (sel == 0) {
                        size_t o = ((size_t)bhd * N_SEQ + nn) * HEAD_DIM + dh;
                        *(uint32_t*)&g_q_f[o] = pack_h2(v0, v1);
                    } else if (sel == 1) {
                        size_t o = ((size_t)bhd * N_SEQ + nn) * HEAD_DIM + dh;
                        *(uint32_t*)&g_k_f[o] = pack_h2(v0, v1);
                    } else {
                        size_t o = ((size_t)bhd * HEAD_DIM + dh) * N_SEQ + nn;
                        g_vt_f[o] = __float2half_rn(v0);
                        g_vt_f[o + N_SEQ] = __float2half_rn(v1);
                    }
                }
            }
        }
    } else {
#pragma unroll
        for (int i = 0; i < 2; i++) {
#pragma unroll
            for (int rr = 0; rr < 2; rr++) {
                const int m = mbase + i * 16 + rr * 8;
                float* cp = C + (size_t)m * N;
#pragma unroll
                for (int j = 0; j < 8; j++) {
#pragma unroll
                    for (int c = 0; c < 2; c++) {
                        const int jg = nbase + j * 8 + c;
                        cp[jg] = acc[i][j][rr * 2 + c] + bias[jg];
                    }
                }
            }
        }
    }
}

// ---------------------------------------------------------------------------
// mma.sync fp16 flash attention, 3-stage cp.async KV ring, 2 CTAs/SM.
// Fragment loads batched ahead of MMA packs (same scheduling fix as GEMM).
// ---------------------------------------------------------------------------
#define AQ_STR 72
#define A_Q_ARR_B (128 * AQ_STR * 2)     // 18432
#define A_KV_ARR_B (64 * AQ_STR * 2)     // 9216
#define A_KV_STAGE_B (2 * A_KV_ARR_B)    // 18432
#define A_KV_BASE A_Q_ARR_B              // 18432
#define ATT_SMEM_BYTES (A_KV_BASE + 3 * A_KV_STAGE_B)   // 73728

__global__ void __launch_bounds__(256, 2)
attn_mma_kernel()
{
    extern __shared__ __align__(16) char dsm[];
    const uint32_t sb0  = smem_u32(dsm);
    const uint32_t q_b  = sb0;

    const int tid  = threadIdx.x;
    const int w    = tid >> 5;
    const int lane = tid & 31;
    const int bh   = blockIdx.y;
    const int qt   = blockIdx.x;

    const __half* ksrc = g_k_f + (size_t)bh * N_SEQ * HEAD_DIM;
    const __half* vsrc = g_vt_f + (size_t)bh * HEAD_DIM * N_SEQ;

    const int f0 = tid, f1 = 256 + tid;
    const int kr0 = f0 >> 3, kc0 = (f0 & 7) << 3;
    const int kr1 = f1 >> 3, kc1 = (f1 & 7) << 3;
    const uint32_t kso0 = ((uint32_t)kr0 * AQ_STR + kc0) * 2;
    const uint32_t kso1 = ((uint32_t)kr1 * AQ_STR + kc1) * 2;

#define A_ISSUE(stage, kt_)                                                     \
    do {                                                                        \
        uint32_t sb = sb0 + A_KV_BASE + (stage) * A_KV_STAGE_B;                 \
        CP16(sb + kso0,               ksrc + (size_t)((kt_) * 64 + kr0) * HEAD_DIM + kc0); \
        CP16(sb + kso1,               ksrc + (size_t)((kt_) * 64 + kr1) * HEAD_DIM + kc1); \
        CP16(sb + A_KV_ARR_B + kso0,  vsrc + (size_t)kr0 * N_SEQ + (kt_) * 64 + kc0); \
        CP16(sb + A_KV_ARR_B + kso1,  vsrc + (size_t)kr1 * N_SEQ + (kt_) * 64 + kc1); \
        CP_COMMIT();                                                            \
    } while (0)

    A_ISSUE(0, 0);
    A_ISSUE(1, 1);

    // Load Q tile [128][64] fp16 (plain loads, once)
    const __half* qsrc = g_q_f + ((size_t)bh * N_SEQ + qt * 128) * HEAD_DIM;
#pragma unroll
    for (int i = 0; i < 4; i++) {
        int f  = i * 256 + tid;
        int r  = f >> 3;
        int c8 = (f & 7) << 3;
        uint32_t so = ((uint32_t)r * AQ_STR + c8) * 2;
        *(uint4*)(dsm + so) = *(const uint4*)(qsrc + r * HEAD_DIM + c8);
    }

    const uint32_t a_row = lane & 15;
    const uint32_t a_kof = (lane >> 4) << 3;
    const uint32_t b_nof = ((lane >> 4) << 3) + (lane & 7);
    const uint32_t b_kof = ((lane >> 3) & 1) << 3;

    float m0 = -1e30f, m1 = -1e30f, l0 = 0.f, l1 = 0.f;
    float o[8][4];
#pragma unroll
    for (int j = 0; j < 8; j++)
#pragma unroll
        for (int c = 0; c < 4; c++) o[j][c] = 0.f;

    const int nkt = N_SEQ / 64;
    for (int kt = 0; kt < nkt; kt++) {
        if (kt + 1 < nkt) { CP_WAIT(1); } else { CP_WAIT(0); }
        __syncthreads();
        if (kt + 2 < nkt) A_ISSUE((kt + 2) % 3, kt + 2);

        const uint32_t sb  = sb0 + A_KV_BASE + (kt % 3) * A_KV_STAGE_B;
        const uint32_t k_b = sb;
        const uint32_t v_b = sb + A_KV_ARR_B;

        // S = Q @ K^T: per k-step, load Q + all 4 K-groups, then 8 MMAs
        float s[8][4];
#pragma unroll
        for (int j = 0; j < 8; j++)
#pragma unroll
            for (int c = 0; c < 4; c++) s[j][c] = 0.f;

#pragma unroll
        for (int t = 0; t < 4; t++) {
            uint32_t q4[4], kf[4][4];
            {
                uint32_t eoff = ((w * 16 + a_row) * AQ_STR + t * 16 + a_kof) * 2;
                LDSM_X4(q4[0], q4[1], q4[2], q4[3], q_b + eoff);
            }
#pragma unroll
            for (int g = 0; g < 4; g++) {
                uint32_t eoff = ((g * 16 + b_nof) * AQ_STR + t * 16 + b_kof) * 2;
                LDSM_X4(kf[g][0], kf[g][1], kf[g][2], kf[g][3], k_b + eoff);
            }
#pragma unroll
            for (int g = 0; g < 4; g++) {
                MMA_F16(s[2 * g + 0], q4, kf[g][0], kf[g][1]);
                MMA_F16(s[2 * g + 1], q4, kf[g][2], kf[g][3]);
            }
        }

        // Row max (fp32) shared by 4-lane groups
        float mx0 = -1e30f, mx1 = -1e30f;
#pragma unroll
        for (int j = 0; j < 8; j++) {
            mx0 = fmaxf(mx0, fmaxf(s[j][0], s[j][1]));
            mx1 = fmaxf(mx1, fmaxf(s[j][2], s[j][3]));
        }
        mx0 = fmaxf(mx0, __shfl_xor_sync(0xffffffffu, mx0, 1));
        mx0 = fmaxf(mx0, __shfl_xor_sync(0xffffffffu, mx0, 2));
        mx1 = fmaxf(mx1, __shfl_xor_sync(0xffffffffu, mx1, 1));
        mx1 = fmaxf(mx1, __shfl_xor_sync(0xffffffffu, mx1, 2));
        float mn0 = fmaxf(m0, mx0), mn1 = fmaxf(m1, mx1);
        float sc0 = fexp2(m0 - mn0), sc1 = fexp2(m1 - mn1);
        m0 = mn0; m1 = mn1;

        // Rescale O before accumulating this tile's PV
#pragma unroll
        for (int j = 0; j < 8; j++) {
            o[j][0] *= sc0; o[j][1] *= sc0;
            o[j][2] *= sc1; o[j][3] *= sc1;
        }

        // P = exp2(S - m) as half2 fragments; O += P @ V with batched V frags;
        // denominator via ones-MMA row sum.
        float lacc[4] = {0.f, 0.f, 0.f, 0.f};
#pragma unroll
        for (int t = 0; t < 4; t++) {
            uint32_t p4[4], vf[4][4];
            p4[0] = h2exp2(pack_h2(s[2 * t][0] - m0,     s[2 * t][1] - m0));
            p4[1] = h2exp2(pack_h2(s[2 * t][2] - m1,     s[2 * t][3] - m1));
            p4[2] = h2exp2(pack_h2(s[2 * t + 1][0] - m0, s[2 * t + 1][1] - m0));
            p4[3] = h2exp2(pack_h2(s[2 * t + 1][2] - m1, s[2 * t + 1][3] - m1));
#pragma unroll
            for (int g = 0; g < 4; g++) {
                uint32_t eoff = ((g * 16 + b_nof) * AQ_STR + t * 16 + b_kof) * 2;
                LDSM_X4(vf[g][0], vf[g][1], vf[g][2], vf[g][3], v_b + eoff);
            }
            MMA_F16(lacc, p4, ONES_H2, ONES_H2);
#pragma unroll
            for (int g = 0; g < 4; g++) {
                MMA_F16(o[2 * g + 0], p4, vf[g][0], vf[g][1]);
                MMA_F16(o[2 * g + 1], p4, vf[g][2], vf[g][3]);
            }
        }
        l0 = l0 * sc0 + lacc[0];
        l1 = l1 * sc1 + lacc[2];
    }
#undef A_ISSUE

    // Epilogue: normalize, write att fp16 [token][h*64+d]
    const float inv0 = 1.0f / l0, inv1 = 1.0f / l1;
    const int b  = bh >> 4;
    const int hh = bh & 15;
    const int r0 = qt * 128 + w * 16 + (lane >> 2);
    const int r1 = r0 + 8;
    const int col0 = hh * HEAD_DIM + ((lane & 3) << 1);
#pragma unroll
    for (int j = 0; j < 8; j++) {
        size_t o0 = (size_t)(b * N_SEQ + r0) * D_MODEL + col0 + 8 * j;
        *(uint32_t*)&g_att_f[o0] = pack_h2(o[j][0] * inv0, o[j][1] * inv0);
        size_t o1 = (size_t)(b * N_SEQ + r1) * D_MODEL + col0 + 8 * j;
        *(uint32_t*)&g_att_f[o1] = pack_h2(o[j][2] * inv1, o[j][3] * inv1);
    }
}

// ---------------------------------------------------------------------------
// Launch
// ---------------------------------------------------------------------------
extern "C" void kernel_launch(void* const* d_in, const int* in_sizes, int n_in,
                              void* d_out, int out_size)
{
    const float* x      = (const float*)d_in[0];
    const float* W_qkv  = (const float*)d_in[1];
    const float* b_qkv  = (const float*)d_in[2];
    const float* W_out  = (const float*)d_in[3];
    const float* b_out  = (const float*)d_in[4];
    float* out = (float*)d_out;

    static __half *xf = nullptr, *wqf, *wof, *atf;
    static bool init_done = false;
    if (!init_done) {
        cudaGetSymbolAddress((void**)&xf,  g_x_f);
        cudaGetSymbolAddress((void**)&wqf, g_wqkv_f);
        cudaGetSymbolAddress((void**)&wof, g_wout_f);
        cudaGetSymbolAddress((void**)&atf, g_att_f);
        cudaFuncSetAttribute(mma_gemm_kernel,
                             cudaFuncAttributeMaxDynamicSharedMemorySize,
                             G_SMEM_B);
        cudaFuncSetAttribute(attn_mma_kernel,
                             cudaFuncAttributeMaxDynamicSharedMemorySize,
                             ATT_SMEM_BYTES);
        init_done = true;
    }

    // 0) fp16 conversions (x + both weight transposes, 2 launches)
    {
        int n4 = (TOKENS * D_MODEL) / 4;
        conv_x_kernel<<<n4 / 256, 256>>>(x, xf, n4);
        dim3 blk(32, 8);
        conv_wt_kernel<<<dim3((QKV_COLS + D_MODEL) / 32, D_MODEL / 32), blk>>>(
            W_qkv, wqf, W_out, wof);
    }

    // 1) QKV projection -> fp16 Q/K/Vt
    {
        dim3 grid(QKV_COLS / 128, TOKENS / 128);
        mma_gemm_kernel<<<grid, 256, G_SMEM_B>>>(xf, wqf, b_qkv, nullptr,
                                                 TOKENS, QKV_COLS, D_MODEL, 0);
    }

    // 2) Flash attention
    {
        dim3 grid(N_SEQ / 128, BH);
        attn_mma_kernel<<<grid, 256, ATT_SMEM_BYTES>>>();
    }

    // 3) Output projection -> fp32 out
    {
        dim3 grid(D_MODEL / 128, TOKENS / 128);
        mma_gemm_kernel<<<grid, 256, G_SMEM_B>>>(atf, wof, b_out, out,
                                                 TOKENS, D_MODEL, D_MODEL, 1);
    }
}

// round 16
// speedup vs baseline: 1.0522x; 1.0522x over previous
#include <cuda_runtime.h>
#include <cuda_fp16.h>
#include <cstdint>

// Problem constants
#define B_SZ 4
#define N_SEQ 2048
#define D_MODEL 1024
#define N_HEADS 16
#define HEAD_DIM 64
#define BH (B_SZ * N_HEADS)          // 64
#define TOKENS (B_SZ * N_SEQ)        // 8192
#define QKV_COLS (3 * D_MODEL)       // 3072

// ---------------------------------------------------------------------------
// Scratch (module-static device memory; no runtime allocation)
// ---------------------------------------------------------------------------
#define QKV_ELEMS ((size_t)BH * N_SEQ * HEAD_DIM)   // 8388608
__device__ __half g_x_f[(size_t)TOKENS * D_MODEL];
__device__ __half g_wqkv_f[(size_t)QKV_COLS * D_MODEL];   // [n][k]
__device__ __half g_wout_f[(size_t)D_MODEL * D_MODEL];    // [n][k]
__device__ __half g_q_f[QKV_ELEMS];   // [bh][n][dh], pre-scaled by 0.125*log2(e)
__device__ __half g_k_f[QKV_ELEMS];   // [bh][n][dh]
__device__ __half g_vt_f[QKV_ELEMS];  // [bh][dh][n]  (transposed)
__device__ __half g_att_f[(size_t)TOKENS * D_MODEL];  // [token][h*64+dh]

// ---------------------------------------------------------------------------
// Helpers
// ---------------------------------------------------------------------------
__device__ __forceinline__ uint32_t smem_u32(const void* p) {
    uint32_t a;
    asm("{ .reg .u64 t; cvta.to.shared.u64 t, %1; cvt.u32.u64 %0, t; }"
        : "=r"(a) : "l"(p));
    return a;
}

__device__ __forceinline__ uint32_t pack_h2(float x, float y) {
    __half2 h = __floats2half2_rn(x, y);
    return *(uint32_t*)&h;
}

__device__ __forceinline__ float fexp2(float x) {
    float y;
    asm("ex2.approx.f32 %0, %1;" : "=f"(y) : "f"(x));
    return y;
}

__device__ __forceinline__ uint32_t h2exp2(uint32_t x) {
    uint32_t y;
    asm("ex2.approx.f16x2 %0, %1;" : "=r"(y) : "r"(x));
    return y;
}

#define ONES_H2 0x3C003C00u   // half2(1.0, 1.0)

#define LDSM_X4(r0, r1, r2, r3, addr) \
    asm volatile("ldmatrix.sync.aligned.m8n8.x4.shared.b16 {%0,%1,%2,%3}, [%4];" \
                 : "=r"(r0), "=r"(r1), "=r"(r2), "=r"(r3) : "r"(addr))

#define MMA_F16(c, a, b0, b1) \
    asm volatile("mma.sync.aligned.m16n8k16.row.col.f32.f16.f16.f32 " \
                 "{%0,%1,%2,%3}, {%4,%5,%6,%7}, {%8,%9}, {%0,%1,%2,%3};" \
                 : "+f"((c)[0]), "+f"((c)[1]), "+f"((c)[2]), "+f"((c)[3]) \
                 : "r"((a)[0]), "r"((a)[1]), "r"((a)[2]), "r"((a)[3]), \
                   "r"(b0), "r"(b1))

#define CP16(saddr, gptr) \
    asm volatile("cp.async.cg.shared.global [%0], [%1], 16;" \
                 :: "r"(saddr), "l"(gptr) : "memory")
#define CP_COMMIT() asm volatile("cp.async.commit_group;" ::: "memory")
#define CP_WAIT(n)  asm volatile("cp.async.wait_group %0;" :: "n"(n) : "memory")

// Q pre-scale: (1/sqrt(64)) * log2(e), so softmax runs in base-2 domain.
#define Q_SCALE 0.1803368801111244f

// ---------------------------------------------------------------------------
// Conversion kernels (fp32 -> fp16)
// ---------------------------------------------------------------------------
__global__ void conv_x_kernel(const float* __restrict__ x, __half* __restrict__ o, int n4)
{
    int idx = blockIdx.x * 256 + threadIdx.x;
    if (idx >= n4) return;
    float4 v = ((const float4*)x)[idx];
    ((uint2*)o)[idx] = make_uint2(pack_h2(v.x, v.y), pack_h2(v.z, v.w));
}

// W[k][n] fp32 -> Wt[n][k] fp16 (tiled transpose)
__global__ void conv_wt_kernel(const float* __restrict__ W, __half* __restrict__ o,
                               int N, int K)
{
    __shared__ float t[32][33];
    const int tx = threadIdx.x, ty = threadIdx.y;  // block (32,8)
    const int n0 = blockIdx.x * 32, k0 = blockIdx.y * 32;
#pragma unroll
    for (int s = 0; s < 4; s++)
        t[ty + 8 * s][tx] = W[(size_t)(k0 + ty + 8 * s) * N + n0 + tx];
    __syncthreads();
#pragma unroll
    for (int s = 0; s < 4; s++) {
        const int nn = ty + 8 * s, kk = tx;
        o[(size_t)(n0 + nn) * K + k0 + kk] = __float2half_rn(t[kk][nn]);
    }
}

// ---------------------------------------------------------------------------
// Warp-MMA fp16 GEMM, BK=64, 3-stage cp.async ring (R14 schedule — best).
// C[M,N] = A[M,K] @ Bt[N,K]^T + bias[N].  BM=BN=128, 256 thr, 8 warps.
// mode 0: QKV epilogue -> fp16 Q/K/Vt; mode 1: fp32 write + bias (float2).
// ---------------------------------------------------------------------------
#define SSTRIDE 72
#define G_ARR_B (128 * SSTRIDE * 2)          // 18432 bytes per array (128x64 fp16)
#define G_STAGE_B (2 * G_ARR_B)              // 36864 per stage (A|B)
#define G_SMEM_B (3 * G_STAGE_B)             // 110592

__global__ void __launch_bounds__(256, 2)
mma_gemm_kernel(const __half* __restrict__ A_g, const __half* __restrict__ B_g,
                const float* __restrict__ bias, float* __restrict__ C,
                int M, int N, int K, int mode)
{
    extern __shared__ __align__(16) char dsm[];
    const uint32_t sb0 = smem_u32(dsm);

    const int tid  = threadIdx.x;
    const int wid  = tid >> 5;
    const int lane = tid & 31;
    const int wr   = wid >> 1;
    const int wc   = wid & 1;

    const int row0 = blockIdx.y * 128;
    const int col0 = blockIdx.x * 128;

    float acc[2][8][4];
#pragma unroll
    for (int i = 0; i < 2; i++)
#pragma unroll
        for (int j = 0; j < 8; j++)
#pragma unroll
            for (int c = 0; c < 4; c++) acc[i][j][c] = 0.f;

    const uint32_t a_row = lane & 15;
    const uint32_t a_kof = (lane >> 4) << 3;
    const uint32_t b_nof = ((lane >> 4) << 3) + (lane & 7);
    const uint32_t b_kof = ((lane >> 3) & 1) << 3;

    uint32_t lso[4];
    const __half* ap[4];
    const __half* bp[4];
#pragma unroll
    for (int i = 0; i < 4; i++) {
        int f = i * 256 + tid;
        int r = f >> 3;
        int c = (f & 7) << 3;
        lso[i] = ((uint32_t)r * SSTRIDE + c) * 2;
        ap[i] = A_g + (size_t)(row0 + r) * K + c;
        bp[i] = B_g + (size_t)(col0 + r) * K + c;
    }

#define G_ISSUE(stage, k0_)                                                     \
    do {                                                                        \
        uint32_t sb = sb0 + (stage) * G_STAGE_B;                                \
        _Pragma("unroll")                                                       \
        for (int i = 0; i < 4; i++) {                                           \
            CP16(sb + lso[i],           ap[i] + (k0_));                         \
            CP16(sb + G_ARR_B + lso[i], bp[i] + (k0_));                         \
        }                                                                       \
        CP_COMMIT();                                                            \
    } while (0)

    const int niter = K / 64;
    G_ISSUE(0, 0);
    G_ISSUE(1, 64);

    for (int it = 0; it < niter; it++) {
        if (it + 1 < niter) { CP_WAIT(1); } else { CP_WAIT(0); }
        __syncthreads();

        const uint32_t sb  = sb0 + (it % 3) * G_STAGE_B;
        const uint32_t a_b = sb;
        const uint32_t b_b = sb + G_ARR_B;

#pragma unroll
        for (int ks = 0; ks < 4; ks++) {
            const uint32_t kk = ks * 16;
            uint32_t ar[2][4];
#pragma unroll
            for (int i = 0; i < 2; i++) {
                uint32_t eoff = ((wr * 32 + i * 16 + a_row) * SSTRIDE + kk + a_kof) * 2;
                LDSM_X4(ar[i][0], ar[i][1], ar[i][2], ar[i][3], a_b + eoff);
            }
#pragma unroll
            for (int jp = 0; jp < 4; jp++) {
                const uint32_t nb = wc * 64 + jp * 16;
                uint32_t eoff = ((nb + b_nof) * SSTRIDE + kk + b_kof) * 2;
                uint32_t br[4];
                LDSM_X4(br[0], br[1], br[2], br[3], b_b + eoff);
#pragma unroll
                for (int i = 0; i < 2; i++) {
                    MMA_F16(acc[i][2 * jp + 0], ar[i], br[0], br[1]);
                    MMA_F16(acc[i][2 * jp + 1], ar[i], br[2], br[3]);
                }
            }
        }
        if (it + 2 < niter) G_ISSUE((it + 2) % 3, (it + 2) * 64);
    }
#undef G_ISSUE

    const int mbase = row0 + wr * 32 + (lane >> 2);
    const int nbase = col0 + wc * 64 + ((lane & 3) << 1);

    if (mode == 0) {
#pragma unroll
        for (int i = 0; i < 2; i++) {
#pragma unroll
            for (int rr = 0; rr < 2; rr++) {
                const int m  = mbase + i * 16 + rr * 8;
                const int bb = m >> 11;
                const int nn = m & 2047;
#pragma unroll
                for (int j = 0; j < 8; j++) {
                    const int jg0 = nbase + j * 8;
                    const int sel = jg0 >> 10;
                    const int hh  = (jg0 >> 6) & 15;
                    const int dh  = jg0 & 63;
                    const int bhd = bb * N_HEADS + hh;
                    float v0 = acc[i][j][rr * 2 + 0] + bias[jg0];
                    float v1 = acc[i][j][rr * 2 + 1] + bias[jg0 + 1];
                    if (sel == 0) { v0 *= Q_SCALE; v1 *= Q_SCALE; }
                    if (sel == 0) {
                        size_t o = ((size_t)bhd * N_SEQ + nn) * HEAD_DIM + dh;
                        *(uint32_t*)&g_q_f[o] = pack_h2(v0, v1);
                    } else if (sel == 1) {
                        size_t o = ((size_t)bhd * N_SEQ + nn) * HEAD_DIM + dh;
                        *(uint32_t*)&g_k_f[o] = pack_h2(v0, v1);
                    } else {
                        size_t o = ((size_t)bhd * HEAD_DIM + dh) * N_SEQ + nn;
                        g_vt_f[o] = __float2half_rn(v0);
                        g_vt_f[o + N_SEQ] = __float2half_rn(v1);
                    }
                }
            }
        }
    } else {
#pragma unroll
        for (int i = 0; i < 2; i++) {
#pragma unroll
            for (int rr = 0; rr < 2; rr++) {
                const int m = mbase + i * 16 + rr * 8;
                float* cp = C + (size_t)m * N;
#pragma unroll
                for (int j = 0; j < 8; j++) {
                    const int jg = nbase + j * 8;
                    float2 v;
                    v.x = acc[i][j][rr * 2 + 0] + bias[jg];
                    v.y = acc[i][j][rr * 2 + 1] + bias[jg + 1];
                    *(float2*)(cp + jg) = v;
                }
            }
        }
    }
}

// ---------------------------------------------------------------------------
// mma.sync fp16 flash attention, 3-stage cp.async KV ring, 2 CTAs/SM.
// R14 schedule (best). Base-2 softmax, f16x2 exp, ones-MMA denominator.
// smem: Q [128][72] fp16 + 3 stages x (K|V) [64][72] fp16 = 73728 B.
// ---------------------------------------------------------------------------
#define AQ_STR 72
#define A_Q_ARR_B (128 * AQ_STR * 2)     // 18432
#define A_KV_ARR_B (64 * AQ_STR * 2)     // 9216
#define A_KV_STAGE_B (2 * A_KV_ARR_B)    // 18432
#define A_KV_BASE A_Q_ARR_B              // 18432
#define ATT_SMEM_BYTES (A_KV_BASE + 3 * A_KV_STAGE_B)   // 73728

__global__ void __launch_bounds__(256, 2)
attn_mma_kernel()
{
    extern __shared__ __align__(16) char dsm[];
    const uint32_t sb0  = smem_u32(dsm);
    const uint32_t q_b  = sb0;

    const int tid  = threadIdx.x;
    const int w    = tid >> 5;
    const int lane = tid & 31;
    const int bh   = blockIdx.y;
    const int qt   = blockIdx.x;

    const __half* ksrc = g_k_f + (size_t)bh * N_SEQ * HEAD_DIM;
    const __half* vsrc = g_vt_f + (size_t)bh * HEAD_DIM * N_SEQ;

    const int f0 = tid, f1 = 256 + tid;
    const int kr0 = f0 >> 3, kc0 = (f0 & 7) << 3;
    const int kr1 = f1 >> 3, kc1 = (f1 & 7) << 3;
    const uint32_t kso0 = ((uint32_t)kr0 * AQ_STR + kc0) * 2;
    const uint32_t kso1 = ((uint32_t)kr1 * AQ_STR + kc1) * 2;

#define A_ISSUE(stage, kt_)                                                     \
    do {                                                                        \
        uint32_t sb = sb0 + A_KV_BASE + (stage) * A_KV_STAGE_B;                 \
        CP16(sb + kso0,               ksrc + (size_t)((kt_) * 64 + kr0) * HEAD_DIM + kc0); \
        CP16(sb + kso1,               ksrc + (size_t)((kt_) * 64 + kr1) * HEAD_DIM + kc1); \
        CP16(sb + A_KV_ARR_B + kso0,  vsrc + (size_t)kr0 * N_SEQ + (kt_) * 64 + kc0); \
        CP16(sb + A_KV_ARR_B + kso1,  vsrc + (size_t)kr1 * N_SEQ + (kt_) * 64 + kc1); \
        CP_COMMIT();                                                            \
    } while (0)

    A_ISSUE(0, 0);
    A_ISSUE(1, 1);

    // Load Q tile [128][64] fp16 (plain loads, once)
    const __half* qsrc = g_q_f + ((size_t)bh * N_SEQ + qt * 128) * HEAD_DIM;
#pragma unroll
    for (int i = 0; i < 4; i++) {
        int f  = i * 256 + tid;
        int r  = f >> 3;
        int c8 = (f & 7) << 3;
        uint32_t so = ((uint32_t)r * AQ_STR + c8) * 2;
        *(uint4*)(dsm + so) = *(const uint4*)(qsrc + r * HEAD_DIM + c8);
    }

    const uint32_t a_row = lane & 15;
    const uint32_t a_kof = (lane >> 4) << 3;
    const uint32_t b_nof = ((lane >> 4) << 3) + (lane & 7);
    const uint32_t b_kof = ((lane >> 3) & 1) << 3;

    float m0 = -1e30f, m1 = -1e30f, l0 = 0.f, l1 = 0.f;
    float o[8][4];
#pragma unroll
    for (int j = 0; j < 8; j++)
#pragma unroll
        for (int c = 0; c < 4; c++) o[j][c] = 0.f;

    const int nkt = N_SEQ / 64;
    for (int kt = 0; kt < nkt; kt++) {
        if (kt + 1 < nkt) { CP_WAIT(1); } else { CP_WAIT(0); }
        __syncthreads();

        const uint32_t sb  = sb0 + A_KV_BASE + (kt % 3) * A_KV_STAGE_B;
        const uint32_t k_b = sb;
        const uint32_t v_b = sb + A_KV_ARR_B;

        // S = Q @ K^T (base-2 scale pre-folded into Q)
        float s[8][4];
#pragma unroll
        for (int j = 0; j < 8; j++)
#pragma unroll
            for (int c = 0; c < 4; c++) s[j][c] = 0.f;

#pragma unroll
        for (int t = 0; t < 4; t++) {
            uint32_t q4[4];
            {
                uint32_t eoff = ((w * 16 + a_row) * AQ_STR + t * 16 + a_kof) * 2;
                LDSM_X4(q4[0], q4[1], q4[2], q4[3], q_b + eoff);
            }
#pragma unroll
            for (int g = 0; g < 4; g++) {
                uint32_t eoff = ((g * 16 + b_nof) * AQ_STR + t * 16 + b_kof) * 2;
                uint32_t k4[4];
                LDSM_X4(k4[0], k4[1], k4[2], k4[3], k_b + eoff);
                MMA_F16(s[2 * g + 0], q4, k4[0], k4[1]);
                MMA_F16(s[2 * g + 1], q4, k4[2], k4[3]);
            }
        }

        // Row max (fp32) shared by 4-lane groups
        float mx0 = -1e30f, mx1 = -1e30f;
#pragma unroll
        for (int j = 0; j < 8; j++) {
            mx0 = fmaxf(mx0, fmaxf(s[j][0], s[j][1]));
            mx1 = fmaxf(mx1, fmaxf(s[j][2], s[j][3]));
        }
        mx0 = fmaxf(mx0, __shfl_xor_sync(0xffffffffu, mx0, 1));
        mx0 = fmaxf(mx0, __shfl_xor_sync(0xffffffffu, mx0, 2));
        mx1 = fmaxf(mx1, __shfl_xor_sync(0xffffffffu, mx1, 1));
        mx1 = fmaxf(mx1, __shfl_xor_sync(0xffffffffu, mx1, 2));
        float mn0 = fmaxf(m0, mx0), mn1 = fmaxf(m1, mx1);
        float sc0 = fexp2(m0 - mn0), sc1 = fexp2(m1 - mn1);
        m0 = mn0; m1 = mn1;

        // Rescale O before accumulating this tile's PV
#pragma unroll
        for (int j = 0; j < 8; j++) {
            o[j][0] *= sc0; o[j][1] *= sc0;
            o[j][2] *= sc1; o[j][3] *= sc1;
        }

        // P = exp2(S - m) as half2 fragments; O += P @ V;
        // denominator via ones-MMA row sum (complete across lanes).
        float lacc[4] = {0.f, 0.f, 0.f, 0.f};
#pragma unroll
        for (int t = 0; t < 4; t++) {
            uint32_t p4[4];
            p4[0] = h2exp2(pack_h2(s[2 * t][0] - m0,     s[2 * t][1] - m0));
            p4[1] = h2exp2(pack_h2(s[2 * t][2] - m1,     s[2 * t][3] - m1));
            p4[2] = h2exp2(pack_h2(s[2 * t + 1][0] - m0, s[2 * t + 1][1] - m0));
            p4[3] = h2exp2(pack_h2(s[2 * t + 1][2] - m1, s[2 * t + 1][3] - m1));
            MMA_F16(lacc, p4, ONES_H2, ONES_H2);
#pragma unroll
            for (int g = 0; g < 4; g++) {
                uint32_t eoff = ((g * 16 + b_nof) * AQ_STR + t * 16 + b_kof) * 2;
                uint32_t v4[4];
                LDSM_X4(v4[0], v4[1], v4[2], v4[3], v_b + eoff);
                MMA_F16(o[2 * g + 0], p4, v4[0], v4[1]);
                MMA_F16(o[2 * g + 1], p4, v4[2], v4[3]);
            }
        }
        l0 = l0 * sc0 + lacc[0];
        l1 = l1 * sc1 + lacc[2];

        if (kt + 2 < nkt) A_ISSUE((kt + 2) % 3, kt + 2);
    }
#undef A_ISSUE

    // Epilogue: normalize, write att fp16 [token][h*64+d]
    const float inv0 = 1.0f / l0, inv1 = 1.0f / l1;
    const int b  = bh >> 4;
    const int hh = bh & 15;
    const int r0 = qt * 128 + w * 16 + (lane >> 2);
    const int r1 = r0 + 8;
    const int col0 = hh * HEAD_DIM + ((lane & 3) << 1);
#pragma unroll
    for (int j = 0; j < 8; j++) {
        size_t o0 = (size_t)(b * N_SEQ + r0) * D_MODEL + col0 + 8 * j;
        *(uint32_t*)&g_att_f[o0] = pack_h2(o[j][0] * inv0, o[j][1] * inv0);
        size_t o1 = (size_t)(b * N_SEQ + r1) * D_MODEL + col0 + 8 * j;
        *(uint32_t*)&g_att_f[o1] = pack_h2(o[j][2] * inv1, o[j][3] * inv1);
    }
}

// ---------------------------------------------------------------------------
// Launch
// ---------------------------------------------------------------------------
extern "C" void kernel_launch(void* const* d_in, const int* in_sizes, int n_in,
                              void* d_out, int out_size)
{
    const float* x      = (const float*)d_in[0];
    const float* W_qkv  = (const float*)d_in[1];
    const float* b_qkv  = (const float*)d_in[2];
    const float* W_out  = (const float*)d_in[3];
    const float* b_out  = (const float*)d_in[4];
    float* out = (float*)d_out;

    static __half *xf = nullptr, *wqf, *wof, *atf;
    static cudaStream_t s_side = nullptr;
    static cudaEvent_t e_fork = nullptr, e_join = nullptr;
    static bool init_done = false;
    if (!init_done) {
        cudaGetSymbolAddress((void**)&xf,  g_x_f);
        cudaGetSymbolAddress((void**)&wqf, g_wqkv_f);
        cudaGetSymbolAddress((void**)&wof, g_wout_f);
        cudaGetSymbolAddress((void**)&atf, g_att_f);
        cudaFuncSetAttribute(mma_gemm_kernel,
                             cudaFuncAttributeMaxDynamicSharedMemorySize,
                             G_SMEM_B);
        cudaFuncSetAttribute(attn_mma_kernel,
                             cudaFuncAttributeMaxDynamicSharedMemorySize,
                             ATT_SMEM_BYTES);
        cudaStreamCreateWithFlags(&s_side, cudaStreamNonBlocking);
        cudaEventCreateWithFlags(&e_fork, cudaEventDisableTiming);
        cudaEventCreateWithFlags(&e_join, cudaEventDisableTiming);
        init_done = true;
    }

    dim3 cblk(32, 8);

    // Fork: W_out transpose runs on the side stream, overlapping QKV+attention.
    cudaEventRecord(e_fork, 0);
    cudaStreamWaitEvent(s_side, e_fork, 0);
    conv_wt_kernel<<<dim3(D_MODEL / 32, D_MODEL / 32), cblk, 0, s_side>>>(
        W_out, wof, D_MODEL, D_MODEL);
    cudaEventRecord(e_join, s_side);

    // 0) fp16 conversions needed by stage 1 (main stream)
    {
        int n4 = (TOKENS * D_MODEL) / 4;
        conv_x_kernel<<<n4 / 256, 256>>>(x, xf, n4);
        conv_wt_kernel<<<dim3(QKV_COLS / 32, D_MODEL / 32), cblk>>>(
            W_qkv, wqf, QKV_COLS, D_MODEL);
    }

    // 1) QKV projection -> fp16 Q/K/Vt
    {
        dim3 grid(QKV_COLS / 128, TOKENS / 128);
        mma_gemm_kernel<<<grid, 256, G_SMEM_B>>>(xf, wqf, b_qkv, nullptr,
                                                 TOKENS, QKV_COLS, D_MODEL, 0);
    }

    // 2) Flash attention
    {
        dim3 grid(N_SEQ / 128, BH);
        attn_mma_kernel<<<grid, 256, ATT_SMEM_BYTES>>>();
    }

    // Join: out-projection needs W_out fp16
    cudaStreamWaitEvent(0, e_join, 0);

    // 3) Output projection -> fp32 out
    {
        dim3 grid(D_MODEL / 128, TOKENS / 128);
        mma_gemm_kernel<<<grid, 256, G_SMEM_B>>>(atf, wof, b_out, out,
                                                 TOKENS, D_MODEL, D_MODEL, 1);
    }
}